// round 1
// baseline (speedup 1.0000x reference)
#include <cuda_runtime.h>

// Problem constants
#define NB 4
#define NT 4096
#define NE 1024
#define HS 64

// Scratch for projected q,k,v  (3 x 4 MB, static device arrays — no allocation)
__device__ float g_q[NB * NT * HS];
__device__ float g_k[NB * NT * HS];
__device__ float g_v[NB * NT * HS];

// ---------------------------------------------------------------------------
// Kernel 1: fused QKV projection.
// C[t,h] = sum_c x[t,c] * W[h,c]   for W in {Wq, Wk, Wv} (blockIdx.x selects).
// Tiled GEMM: BM=64 rows, BN=64 (full head dim), BK=32. 256 threads, 4x4 micro.
// ---------------------------------------------------------------------------
__global__ __launch_bounds__(256) void qkv_kernel(
    const float* __restrict__ x,
    const float* __restrict__ Wq,
    const float* __restrict__ Wk,
    const float* __restrict__ Wv)
{
    __shared__ float Xs[32][68];   // [c][m], pad to 68 for conflict-free access
    __shared__ float Ws[32][68];   // [c][h]

    const int tid = threadIdx.x;
    const int tx = tid & 15;
    const int ty = tid >> 4;
    const int m0 = ty * 4;
    const int h0 = tx * 4;
    const int mbase = blockIdx.y * 64;

    const float* __restrict__ W =
        (blockIdx.x == 0) ? Wq : ((blockIdx.x == 1) ? Wk : Wv);
    float* __restrict__ out =
        (blockIdx.x == 0) ? g_q : ((blockIdx.x == 1) ? g_k : g_v);

    float acc[4][4] = {};

    for (int kb = 0; kb < NE; kb += 32) {
        // Load X tile [64 rows x 32 c] and W tile [64 h x 32 c], coalesced on c.
        #pragma unroll
        for (int i = 0; i < 8; i++) {
            int idx = tid + i * 256;        // 0..2047
            int c = idx & 31;
            int r = idx >> 5;               // 0..63
            Xs[c][r] = x[(size_t)(mbase + r) * NE + kb + c];
            Ws[c][r] = W[(size_t)r * NE + kb + c];
        }
        __syncthreads();

        #pragma unroll 8
        for (int c = 0; c < 32; c++) {
            float a[4], bvals[4];
            #pragma unroll
            for (int j = 0; j < 4; j++) a[j] = Xs[c][m0 + j];
            #pragma unroll
            for (int i = 0; i < 4; i++) bvals[i] = Ws[c][h0 + i];
            #pragma unroll
            for (int j = 0; j < 4; j++)
                #pragma unroll
                for (int i = 0; i < 4; i++)
                    acc[j][i] += a[j] * bvals[i];
        }
        __syncthreads();
    }

    #pragma unroll
    for (int j = 0; j < 4; j++)
        #pragma unroll
        for (int i = 0; i < 4; i++)
            out[(size_t)(mbase + m0 + j) * HS + h0 + i] = acc[j][i];
}

// ---------------------------------------------------------------------------
// Kernel 2: causal flash attention, fp32.
// Each block handles TWO query tiles (qt and 63-qt) for load balance:
// (qt+1) + (64-qt) = 65 key tiles per block, uniform across the grid.
// Grid: (32, NB). 256 threads, 16x16 layout, 4x4 micro-tiles.
// Smem: Qs,Ks,Vs each 64x68 fp32 (P overwrites Ks after S is consumed).
// ---------------------------------------------------------------------------
#define LDW 68   // padded row stride (floats); 68%4==0 -> float4-aligned rows

__global__ __launch_bounds__(256) void attn_kernel(float* __restrict__ o)
{
    extern __shared__ float sm[];
    float* Qs = sm;                  // 64*LDW
    float* Ks = sm + 64 * LDW;       // also reused as P buffer
    float* Vs = sm + 2 * 64 * LDW;

    const int tid = threadIdx.x;
    const int tx = tid & 15;
    const int ty = tid >> 4;
    const int m0 = ty * 4;           // query rows within tile
    const int n0 = tx * 4;           // key cols within tile (S compute)
    const int d0 = tx * 4;           // head dims (O accumulate)
    const int b  = blockIdx.y;
    const float scale = 0.125f;      // 1/sqrt(64)

    for (int half = 0; half < 2; half++) {
        const int qt = (half == 0) ? (int)blockIdx.x : 63 - (int)blockIdx.x;
        const int qrow = b * NT + qt * 64;

        __syncthreads();   // protect smem from previous half's readers
        // Load Q tile (float4, coalesced)
        #pragma unroll
        for (int i = 0; i < 4; i++) {
            int lin = (tid + i * 256) * 4;
            int r = lin >> 6;
            int d = lin & 63;
            *(float4*)&Qs[r * LDW + d] =
                *(const float4*)&g_q[(size_t)(qrow + r) * HS + d];
        }

        float oacc[4][4] = {};
        float mi[4] = {-1e30f, -1e30f, -1e30f, -1e30f};
        float li[4] = {0.f, 0.f, 0.f, 0.f};

        for (int kt = 0; kt <= qt; kt++) {
            const int krow = b * NT + kt * 64;
            __syncthreads();   // prior iteration done reading Ks/Vs (also Q-load fence path)
            #pragma unroll
            for (int i = 0; i < 4; i++) {
                int lin = (tid + i * 256) * 4;
                int r = lin >> 6;
                int d = lin & 63;
                *(float4*)&Ks[r * LDW + d] =
                    *(const float4*)&g_k[(size_t)(krow + r) * HS + d];
                *(float4*)&Vs[r * LDW + d] =
                    *(const float4*)&g_v[(size_t)(krow + r) * HS + d];
            }
            __syncthreads();

            // S = Q K^T  (4x4 micro, float4 over the contraction dim)
            float s[4][4] = {};
            #pragma unroll 4
            for (int c = 0; c < 64; c += 4) {
                float4 a[4], kk[4];
                #pragma unroll
                for (int j = 0; j < 4; j++) a[j] = *(float4*)&Qs[(m0 + j) * LDW + c];
                #pragma unroll
                for (int i = 0; i < 4; i++) kk[i] = *(float4*)&Ks[(n0 + i) * LDW + c];
                #pragma unroll
                for (int j = 0; j < 4; j++)
                    #pragma unroll
                    for (int i = 0; i < 4; i++)
                        s[j][i] += a[j].x * kk[i].x + a[j].y * kk[i].y
                                 + a[j].z * kk[i].z + a[j].w * kk[i].w;
            }

            // Mask (diagonal tile) + scale
            const bool diag = (kt == qt);
            #pragma unroll
            for (int j = 0; j < 4; j++)
                #pragma unroll
                for (int i = 0; i < 4; i++) {
                    if (diag && (n0 + i) > (m0 + j)) s[j][i] = -1e30f;
                    else                              s[j][i] *= scale;
                }

            // Online softmax (row reductions across the 16 lanes sharing a row)
            float corr[4];
            #pragma unroll
            for (int j = 0; j < 4; j++) {
                float rm = fmaxf(fmaxf(s[j][0], s[j][1]), fmaxf(s[j][2], s[j][3]));
                #pragma unroll
                for (int off = 8; off >= 1; off >>= 1)
                    rm = fmaxf(rm, __shfl_xor_sync(0xffffffffu, rm, off));
                float mnew = fmaxf(mi[j], rm);
                corr[j] = __expf(mi[j] - mnew);
                float rsum = 0.f;
                #pragma unroll
                for (int i = 0; i < 4; i++) {
                    s[j][i] = __expf(s[j][i] - mnew);
                    rsum += s[j][i];
                }
                #pragma unroll
                for (int off = 8; off >= 1; off >>= 1)
                    rsum += __shfl_xor_sync(0xffffffffu, rsum, off);
                li[j] = li[j] * corr[j] + rsum;
                mi[j] = mnew;
                #pragma unroll
                for (int i = 0; i < 4; i++) oacc[j][i] *= corr[j];
            }

            __syncthreads();   // everyone finished reading Ks
            // Write P into the Ks buffer
            #pragma unroll
            for (int j = 0; j < 4; j++)
                #pragma unroll
                for (int i = 0; i < 4; i++)
                    Ks[(m0 + j) * LDW + n0 + i] = s[j][i];
            __syncthreads();

            // O += P @ V
            #pragma unroll 8
            for (int k = 0; k < 64; k++) {
                float4 vv = *(float4*)&Vs[k * LDW + d0];
                #pragma unroll
                for (int j = 0; j < 4; j++) {
                    float p = Ks[(m0 + j) * LDW + k];
                    oacc[j][0] += p * vv.x;
                    oacc[j][1] += p * vv.y;
                    oacc[j][2] += p * vv.z;
                    oacc[j][3] += p * vv.w;
                }
            }
        }

        // Normalize and write output
        #pragma unroll
        for (int j = 0; j < 4; j++) {
            float inv = 1.0f / li[j];
            #pragma unroll
            for (int i = 0; i < 4; i++)
                o[(size_t)(qrow + m0 + j) * HS + d0 + i] = oacc[j][i] * inv;
        }
    }
}

// ---------------------------------------------------------------------------
extern "C" void kernel_launch(void* const* d_in, const int* in_sizes, int n_in,
                              void* d_out, int out_size)
{
    const float* x  = (const float*)d_in[0];
    const float* Wq = (const float*)d_in[1];
    const float* Wk = (const float*)d_in[2];
    const float* Wv = (const float*)d_in[3];
    float* out = (float*)d_out;

    (void)in_sizes; (void)n_in; (void)out_size;

    qkv_kernel<<<dim3(3, 256), 256>>>(x, Wq, Wk, Wv);

    const int smem = 3 * 64 * LDW * (int)sizeof(float);   // 52224 bytes
    cudaFuncSetAttribute(attn_kernel,
                         cudaFuncAttributeMaxDynamicSharedMemorySize, smem);
    attn_kernel<<<dim3(32, NB), 256, smem>>>(out);
}

// round 4
// speedup vs baseline: 2.4487x; 2.4487x over previous
#include <cuda_runtime.h>
#include <cuda_bf16.h>
#include <cstdint>

#define NB 4
#define NT 4096
#define NE 1024
#define HS 64

// Scratch (static device arrays — no allocation)
__device__ float g_q[NB * NT * HS];
__device__ float g_k[NB * NT * HS];
__device__ float g_vt[NB * HS * NT];   // V transposed: [b][d][t]

// ---------------------------------------------------------------------------
// Helpers
// ---------------------------------------------------------------------------

// split fp32 pair into bf16 hi-pair and lo-pair (packed bf16x2)
__device__ __forceinline__ void split2(float a, float b, uint32_t& hi, uint32_t& lo) {
    __nv_bfloat162 h2 = __floats2bfloat162_rn(a, b);
    float2 hf = __bfloat1622float2(h2);
    __nv_bfloat162 l2 = __floats2bfloat162_rn(a - hf.x, b - hf.y);
    hi = *reinterpret_cast<uint32_t*>(&h2);
    lo = *reinterpret_cast<uint32_t*>(&l2);
}

// mma.sync m16n8k16 bf16 -> f32 accumulate (HMMA; baseline sm_80+ feature)
__device__ __forceinline__ void mma16816(float* c, const uint32_t* a,
                                         uint32_t b0, uint32_t b1) {
    asm volatile(
        "mma.sync.aligned.m16n8k16.row.col.f32.bf16.bf16.f32 "
        "{%0,%1,%2,%3}, {%4,%5,%6,%7}, {%8,%9}, {%0,%1,%2,%3};"
        : "+f"(c[0]), "+f"(c[1]), "+f"(c[2]), "+f"(c[3])
        : "r"(a[0]), "r"(a[1]), "r"(a[2]), "r"(a[3]), "r"(b0), "r"(b1));
}

#define ROWB 144   // padded smem row stride in bytes (64 bf16 + 8 pad)

// ===========================================================================
// Stage 1: fused QKV projection on HMMA (split bf16, 3 passes).
// CTA: 128 x-rows, all 192 output cols (q|k|v). 8 warps x 16 rows.
// ===========================================================================
#define QKV_XH 0
#define QKV_XL 18432          // 128*144
#define QKV_WH 36864
#define QKV_WL 64512          // + 192*144
#define QKV_SMEM 92160

__global__ __launch_bounds__(256, 1) void qkv_mma(
    const float* __restrict__ x,
    const float* __restrict__ Wq,
    const float* __restrict__ Wk,
    const float* __restrict__ Wv)
{
    extern __shared__ __align__(16) char sm[];
    char* Xh = sm + QKV_XH;
    char* Xl = sm + QKV_XL;
    char* Wh = sm + QKV_WH;
    char* Wl = sm + QKV_WL;

    const int tid = threadIdx.x;
    const int wid = tid >> 5;
    const int lane = tid & 31;
    const int g  = lane >> 2;
    const int t3 = lane & 3;
    const int rowblk = blockIdx.x * 128;

    float c[24][4];
    #pragma unroll
    for (int nt = 0; nt < 24; nt++)
        #pragma unroll
        for (int i = 0; i < 4; i++) c[nt][i] = 0.f;

    for (int kc = 0; kc < NE; kc += 64) {
        __syncthreads();
        // ---- load X chunk [128 x 64], split hi/lo ----
        {
            const int r  = tid >> 1;
            const int c0 = (tid & 1) * 32;
            const float4* src = (const float4*)&x[(size_t)(rowblk + r) * NE + kc + c0];
            uint32_t hp[16], lp[16];
            #pragma unroll
            for (int i = 0; i < 8; i++) {
                float4 v = src[i];
                split2(v.x, v.y, hp[2*i],   lp[2*i]);
                split2(v.z, v.w, hp[2*i+1], lp[2*i+1]);
            }
            const int ob = r * ROWB + c0 * 2;
            #pragma unroll
            for (int i = 0; i < 4; i++) {
                *(uint4*)(Xh + ob + 16*i) = make_uint4(hp[4*i], hp[4*i+1], hp[4*i+2], hp[4*i+3]);
                *(uint4*)(Xl + ob + 16*i) = make_uint4(lp[4*i], lp[4*i+1], lp[4*i+2], lp[4*i+3]);
            }
        }
        // ---- load W chunk [192 x 64] (rows 0-63 Wq, 64-127 Wk, 128-191 Wv) ----
        if (tid < 192) {
            const float* Wsel = (tid < 64) ? Wq : ((tid < 128) ? Wk : Wv);
            const int wr = tid & 63;
            const float4* src = (const float4*)&Wsel[(size_t)wr * NE + kc];
            uint32_t hp[32], lp[32];
            #pragma unroll
            for (int i = 0; i < 16; i++) {
                float4 v = src[i];
                split2(v.x, v.y, hp[2*i],   lp[2*i]);
                split2(v.z, v.w, hp[2*i+1], lp[2*i+1]);
            }
            const int ob = tid * ROWB;
            #pragma unroll
            for (int i = 0; i < 8; i++) {
                *(uint4*)(Wh + ob + 16*i) = make_uint4(hp[4*i], hp[4*i+1], hp[4*i+2], hp[4*i+3]);
                *(uint4*)(Wl + ob + 16*i) = make_uint4(lp[4*i], lp[4*i+1], lp[4*i+2], lp[4*i+3]);
            }
        }
        __syncthreads();

        // ---- HMMA: 4 k-steps x 24 n-tiles x 3 split passes ----
        const int rb = (wid * 16 + g) * ROWB;
        #pragma unroll
        for (int ks = 0; ks < 4; ks++) {
            const int colb = ks * 32 + t3 * 4;
            uint32_t ah[4], al[4];
            ah[0] = *(uint32_t*)(Xh + rb + colb);
            ah[1] = *(uint32_t*)(Xh + rb + 8*ROWB + colb);
            ah[2] = *(uint32_t*)(Xh + rb + colb + 16);
            ah[3] = *(uint32_t*)(Xh + rb + 8*ROWB + colb + 16);
            al[0] = *(uint32_t*)(Xl + rb + colb);
            al[1] = *(uint32_t*)(Xl + rb + 8*ROWB + colb);
            al[2] = *(uint32_t*)(Xl + rb + colb + 16);
            al[3] = *(uint32_t*)(Xl + rb + 8*ROWB + colb + 16);
            #pragma unroll
            for (int nt = 0; nt < 24; nt++) {
                const int ab = (nt * 8 + g) * ROWB + colb;
                uint32_t bh0 = *(uint32_t*)(Wh + ab);
                uint32_t bh1 = *(uint32_t*)(Wh + ab + 16);
                uint32_t bl0 = *(uint32_t*)(Wl + ab);
                uint32_t bl1 = *(uint32_t*)(Wl + ab + 16);
                mma16816(c[nt], ah, bh0, bh1);
                mma16816(c[nt], ah, bl0, bl1);
                mma16816(c[nt], al, bh0, bh1);
            }
        }
    }

    // ---- store q, k directly from fragments ----
    const int r0 = rowblk + wid * 16 + g;
    #pragma unroll
    for (int nt = 0; nt < 8; nt++) {
        const int col = nt * 8 + t3 * 2;
        *(float2*)&g_q[(size_t)r0 * HS + col]       = make_float2(c[nt][0], c[nt][1]);
        *(float2*)&g_q[(size_t)(r0 + 8) * HS + col] = make_float2(c[nt][2], c[nt][3]);
    }
    #pragma unroll
    for (int nt = 8; nt < 16; nt++) {
        const int col = nt * 8 + t3 * 2 - 64;
        *(float2*)&g_k[(size_t)r0 * HS + col]       = make_float2(c[nt][0], c[nt][1]);
        *(float2*)&g_k[(size_t)(r0 + 8) * HS + col] = make_float2(c[nt][2], c[nt][3]);
    }

    // ---- V: stage to smem, write transposed coalesced ----
    __syncthreads();
    float* Vs = (float*)sm;       // [64][132] floats = 33792 B (fits in dead X area)
    const int rloc = wid * 16 + g;
    #pragma unroll
    for (int nt = 16; nt < 24; nt++) {
        const int n = nt * 8 + t3 * 2 - 128;
        Vs[n * 132 + rloc]             = c[nt][0];
        Vs[(n + 1) * 132 + rloc]       = c[nt][1];
        Vs[n * 132 + rloc + 8]         = c[nt][2];
        Vs[(n + 1) * 132 + rloc + 8]   = c[nt][3];
    }
    __syncthreads();
    {
        const int d  = tid >> 2;
        const int cc = (tid & 3) * 32;
        const int bb = rowblk >> 12;
        const int t0 = rowblk & (NT - 1);
        float* dst = &g_vt[((size_t)bb * HS + d) * NT + t0 + cc];
        #pragma unroll
        for (int i = 0; i < 8; i++) {
            float4 v = *(float4*)&Vs[d * 132 + cc + 4*i];
            *(float4*)(dst + 4*i) = v;
        }
    }
}

// ===========================================================================
// Stage 2: causal flash attention on HMMA (split bf16, P in registers).
// CTA: 128-row Q tile, 8 warps x 16 rows, kv tiles of 64.
// ===========================================================================
#define AT_QH 0
#define AT_QL 18432
#define AT_KH 36864           // + 64*144 = 9216
#define AT_KL 46080
#define AT_VH 55296
#define AT_VL 64512
#define AT_SMEM 73728

__global__ __launch_bounds__(256, 1) void attn_mma(float* __restrict__ o)
{
    extern __shared__ __align__(16) char sm[];
    char* Qh = sm + AT_QH;
    char* Ql = sm + AT_QL;
    char* Kh = sm + AT_KH;
    char* Kl = sm + AT_KL;
    char* Vh = sm + AT_VH;
    char* Vl = sm + AT_VL;

    const int tid = threadIdx.x;
    const int wid = tid >> 5;
    const int lane = tid & 31;
    const int g  = lane >> 2;
    const int t3 = lane & 3;
    const int qt = blockIdx.x;
    const int b  = blockIdx.y;
    const int qrow = b * NT + qt * 128;

    // ---- load Q tile once: scale 1/8, split ----
    {
        const int r  = tid >> 1;
        const int c0 = (tid & 1) * 32;
        const float4* src = (const float4*)&g_q[(size_t)(qrow + r) * HS + c0];
        uint32_t hp[16], lp[16];
        #pragma unroll
        for (int i = 0; i < 8; i++) {
            float4 v = src[i];
            split2(v.x * 0.125f, v.y * 0.125f, hp[2*i],   lp[2*i]);
            split2(v.z * 0.125f, v.w * 0.125f, hp[2*i+1], lp[2*i+1]);
        }
        const int ob = r * ROWB + c0 * 2;
        #pragma unroll
        for (int i = 0; i < 4; i++) {
            *(uint4*)(Qh + ob + 16*i) = make_uint4(hp[4*i], hp[4*i+1], hp[4*i+2], hp[4*i+3]);
            *(uint4*)(Ql + ob + 16*i) = make_uint4(lp[4*i], lp[4*i+1], lp[4*i+2], lp[4*i+3]);
        }
    }
    __syncthreads();

    // ---- preload Q fragments to registers (persistent) ----
    uint32_t qh[4][4], ql[4][4];
    {
        const int rb = (wid * 16 + g) * ROWB;
        #pragma unroll
        for (int ks = 0; ks < 4; ks++) {
            const int colb = ks * 32 + t3 * 4;
            qh[ks][0] = *(uint32_t*)(Qh + rb + colb);
            qh[ks][1] = *(uint32_t*)(Qh + rb + 8*ROWB + colb);
            qh[ks][2] = *(uint32_t*)(Qh + rb + colb + 16);
            qh[ks][3] = *(uint32_t*)(Qh + rb + 8*ROWB + colb + 16);
            ql[ks][0] = *(uint32_t*)(Ql + rb + colb);
            ql[ks][1] = *(uint32_t*)(Ql + rb + 8*ROWB + colb);
            ql[ks][2] = *(uint32_t*)(Ql + rb + colb + 16);
            ql[ks][3] = *(uint32_t*)(Ql + rb + 8*ROWB + colb + 16);
        }
    }

    float oacc[8][4];
    #pragma unroll
    for (int nt = 0; nt < 8; nt++)
        #pragma unroll
        for (int i = 0; i < 4; i++) oacc[nt][i] = 0.f;
    float mi0 = -1e30f, mi1 = -1e30f, li0 = 0.f, li1 = 0.f;

    const int rA = qt * 128 + wid * 16 + g;   // row of c0,c1
    const int rB = rA + 8;                    // row of c2,c3
    const int nkt = 2 * qt + 2;

    for (int kt = 0; kt < nkt; kt++) {
        __syncthreads();
        // ---- load K and Vt tiles, split hi/lo ----
        {
            const int r  = tid >> 2;
            const int c0 = (tid & 3) * 16;
            const float4* ksrc = (const float4*)&g_k[(size_t)(b * NT + kt * 64 + r) * HS + c0];
            const float4* vsrc = (const float4*)&g_vt[((size_t)b * HS + r) * NT + kt * 64 + c0];
            uint32_t kh[8], kl[8], vh[8], vl[8];
            #pragma unroll
            for (int i = 0; i < 4; i++) {
                float4 kv = ksrc[i];
                split2(kv.x, kv.y, kh[2*i],   kl[2*i]);
                split2(kv.z, kv.w, kh[2*i+1], kl[2*i+1]);
                float4 vv = vsrc[i];
                split2(vv.x, vv.y, vh[2*i],   vl[2*i]);
                split2(vv.z, vv.w, vh[2*i+1], vl[2*i+1]);
            }
            const int ob = r * ROWB + c0 * 2;
            *(uint4*)(Kh + ob)      = make_uint4(kh[0], kh[1], kh[2], kh[3]);
            *(uint4*)(Kh + ob + 16) = make_uint4(kh[4], kh[5], kh[6], kh[7]);
            *(uint4*)(Kl + ob)      = make_uint4(kl[0], kl[1], kl[2], kl[3]);
            *(uint4*)(Kl + ob + 16) = make_uint4(kl[4], kl[5], kl[6], kl[7]);
            *(uint4*)(Vh + ob)      = make_uint4(vh[0], vh[1], vh[2], vh[3]);
            *(uint4*)(Vh + ob + 16) = make_uint4(vh[4], vh[5], vh[6], vh[7]);
            *(uint4*)(Vl + ob)      = make_uint4(vl[0], vl[1], vl[2], vl[3]);
            *(uint4*)(Vl + ob + 16) = make_uint4(vl[4], vl[5], vl[6], vl[7]);
        }
        __syncthreads();

        // ---- S = Q K^T ----
        float s[8][4];
        #pragma unroll
        for (int nt = 0; nt < 8; nt++)
            #pragma unroll
            for (int i = 0; i < 4; i++) s[nt][i] = 0.f;
        #pragma unroll
        for (int ks = 0; ks < 4; ks++) {
            const int colb = ks * 32 + t3 * 4;
            #pragma unroll
            for (int nt = 0; nt < 8; nt++) {
                const int ab = (nt * 8 + g) * ROWB + colb;
                uint32_t bh0 = *(uint32_t*)(Kh + ab);
                uint32_t bh1 = *(uint32_t*)(Kh + ab + 16);
                uint32_t bl0 = *(uint32_t*)(Kl + ab);
                uint32_t bl1 = *(uint32_t*)(Kl + ab + 16);
                mma16816(s[nt], qh[ks], bh0, bh1);
                mma16816(s[nt], qh[ks], bl0, bl1);
                mma16816(s[nt], ql[ks], bh0, bh1);
            }
        }

        // ---- causal mask (only partial tiles) ----
        if (kt >= 2 * qt) {
            #pragma unroll
            for (int nt = 0; nt < 8; nt++) {
                const int col0 = kt * 64 + nt * 8 + t3 * 2;
                if (col0 > rA)     s[nt][0] = -1e30f;
                if (col0 + 1 > rA) s[nt][1] = -1e30f;
                if (col0 > rB)     s[nt][2] = -1e30f;
                if (col0 + 1 > rB) s[nt][3] = -1e30f;
            }
        }

        // ---- online softmax (rows rA, rB; reduce over 4-lane group) ----
        float m0 = -1e30f, m1 = -1e30f;
        #pragma unroll
        for (int nt = 0; nt < 8; nt++) {
            m0 = fmaxf(m0, fmaxf(s[nt][0], s[nt][1]));
            m1 = fmaxf(m1, fmaxf(s[nt][2], s[nt][3]));
        }
        m0 = fmaxf(m0, __shfl_xor_sync(0xffffffffu, m0, 1));
        m0 = fmaxf(m0, __shfl_xor_sync(0xffffffffu, m0, 2));
        m1 = fmaxf(m1, __shfl_xor_sync(0xffffffffu, m1, 1));
        m1 = fmaxf(m1, __shfl_xor_sync(0xffffffffu, m1, 2));
        const float mn0 = fmaxf(mi0, m0);
        const float mn1 = fmaxf(mi1, m1);
        const float corr0 = __expf(mi0 - mn0);
        const float corr1 = __expf(mi1 - mn1);

        float p[8][4];
        float sum0 = 0.f, sum1 = 0.f;
        #pragma unroll
        for (int nt = 0; nt < 8; nt++) {
            p[nt][0] = __expf(s[nt][0] - mn0);
            p[nt][1] = __expf(s[nt][1] - mn0);
            p[nt][2] = __expf(s[nt][2] - mn1);
            p[nt][3] = __expf(s[nt][3] - mn1);
            sum0 += p[nt][0] + p[nt][1];
            sum1 += p[nt][2] + p[nt][3];
        }
        sum0 += __shfl_xor_sync(0xffffffffu, sum0, 1);
        sum0 += __shfl_xor_sync(0xffffffffu, sum0, 2);
        sum1 += __shfl_xor_sync(0xffffffffu, sum1, 1);
        sum1 += __shfl_xor_sync(0xffffffffu, sum1, 2);
        li0 = li0 * corr0 + sum0;  mi0 = mn0;
        li1 = li1 * corr1 + sum1;  mi1 = mn1;

        #pragma unroll
        for (int nt = 0; nt < 8; nt++) {
            oacc[nt][0] *= corr0;  oacc[nt][1] *= corr0;
            oacc[nt][2] *= corr1;  oacc[nt][3] *= corr1;
        }

        // ---- pack P into A-fragments (hi + exact lo residual) ----
        uint32_t pha[4][4], pla[4][4];
        #pragma unroll
        for (int ks = 0; ks < 4; ks++) {
            split2(p[2*ks][0],   p[2*ks][1],   pha[ks][0], pla[ks][0]);
            split2(p[2*ks][2],   p[2*ks][3],   pha[ks][1], pla[ks][1]);
            split2(p[2*ks+1][0], p[2*ks+1][1], pha[ks][2], pla[ks][2]);
            split2(p[2*ks+1][2], p[2*ks+1][3], pha[ks][3], pla[ks][3]);
        }

        // ---- O += P V ----
        #pragma unroll
        for (int ks = 0; ks < 4; ks++) {
            const int colb = ks * 32 + t3 * 4;
            #pragma unroll
            for (int nt = 0; nt < 8; nt++) {
                const int ab = (nt * 8 + g) * ROWB + colb;
                uint32_t bh0 = *(uint32_t*)(Vh + ab);
                uint32_t bh1 = *(uint32_t*)(Vh + ab + 16);
                uint32_t bl0 = *(uint32_t*)(Vl + ab);
                uint32_t bl1 = *(uint32_t*)(Vl + ab + 16);
                mma16816(oacc[nt], pha[ks], bh0, bh1);
                mma16816(oacc[nt], pha[ks], bl0, bl1);
                mma16816(oacc[nt], pla[ks], bh0, bh1);
            }
        }
    }

    // ---- epilogue: normalize, store ----
    const float inv0 = 1.0f / li0;
    const float inv1 = 1.0f / li1;
    const int orow = qrow + wid * 16 + g;
    #pragma unroll
    for (int nt = 0; nt < 8; nt++) {
        const int col = nt * 8 + t3 * 2;
        *(float2*)&o[(size_t)orow * HS + col] =
            make_float2(oacc[nt][0] * inv0, oacc[nt][1] * inv0);
        *(float2*)&o[(size_t)(orow + 8) * HS + col] =
            make_float2(oacc[nt][2] * inv1, oacc[nt][3] * inv1);
    }
}

// ===========================================================================
extern "C" void kernel_launch(void* const* d_in, const int* in_sizes, int n_in,
                              void* d_out, int out_size)
{
    const float* x  = (const float*)d_in[0];
    const float* Wq = (const float*)d_in[1];
    const float* Wk = (const float*)d_in[2];
    const float* Wv = (const float*)d_in[3];
    float* out = (float*)d_out;
    (void)in_sizes; (void)n_in; (void)out_size;

    cudaFuncSetAttribute(qkv_mma, cudaFuncAttributeMaxDynamicSharedMemorySize,
                         QKV_SMEM);
    qkv_mma<<<128, 256, QKV_SMEM>>>(x, Wq, Wk, Wv);

    cudaFuncSetAttribute(attn_mma, cudaFuncAttributeMaxDynamicSharedMemorySize,
                         AT_SMEM);
    attn_mma<<<dim3(32, NB), 256, AT_SMEM>>>(out);
}

// round 5
// speedup vs baseline: 3.2717x; 1.3361x over previous
#include <cuda_runtime.h>
#include <cuda_bf16.h>
#include <cstdint>

#define NB 4
#define NT 4096
#define NE 1024
#define HS 64

// Scratch (static device arrays — no allocation)
__device__ float    g_q[NB * NT * HS];
__device__ uint32_t g_khp[NB * NT * 32];     // K hi, bf16x2 pairs along d
__device__ uint32_t g_klp[NB * NT * 32];     // K lo
__device__ uint32_t g_vthp[NB * HS * 2048];  // V^T hi, [b][d][t-pairs]
__device__ uint32_t g_vtlp[NB * HS * 2048];  // V^T lo

// ---------------------------------------------------------------------------
// Helpers
// ---------------------------------------------------------------------------
__device__ __forceinline__ void split2(float a, float b, uint32_t& hi, uint32_t& lo) {
    __nv_bfloat162 h2 = __floats2bfloat162_rn(a, b);
    float2 hf = __bfloat1622float2(h2);
    __nv_bfloat162 l2 = __floats2bfloat162_rn(a - hf.x, b - hf.y);
    hi = *reinterpret_cast<uint32_t*>(&h2);
    lo = *reinterpret_cast<uint32_t*>(&l2);
}

__device__ __forceinline__ void mma16816(float* c, const uint32_t* a,
                                         uint32_t b0, uint32_t b1) {
    asm volatile(
        "mma.sync.aligned.m16n8k16.row.col.f32.bf16.bf16.f32 "
        "{%0,%1,%2,%3}, {%4,%5,%6,%7}, {%8,%9}, {%0,%1,%2,%3};"
        : "+f"(c[0]), "+f"(c[1]), "+f"(c[2]), "+f"(c[3])
        : "r"(a[0]), "r"(a[1]), "r"(a[2]), "r"(a[3]), "r"(b0), "r"(b1));
}

__device__ __forceinline__ void ldsm4(uint32_t* r, uint32_t addr) {
    asm volatile("ldmatrix.sync.aligned.m8n8.x4.shared.b16 {%0,%1,%2,%3}, [%4];"
                 : "=r"(r[0]), "=r"(r[1]), "=r"(r[2]), "=r"(r[3]) : "r"(addr));
}

__device__ __forceinline__ uint32_t smem_u32(const void* p) {
    uint32_t a;
    asm("{ .reg .u64 t; cvta.to.shared.u64 t, %1; cvt.u32.u64 %0, t; }"
        : "=r"(a) : "l"(p));
    return a;
}

__device__ __forceinline__ void cp16(uint32_t s, const void* g) {
    asm volatile("cp.async.cg.shared.global [%0], [%1], 16;"
                 :: "r"(s), "l"(__cvta_generic_to_global(g)) : "memory");
}

#define ROWB 144   // padded smem row stride (128 data + 16 pad) — conflict-free ldmatrix

// ===========================================================================
// Stage 1: fused QKV projection on HMMA. Writes Q fp32, K/V^T split bf16.
// ===========================================================================
#define QKV_XH 0
#define QKV_XL 18432
#define QKV_WH 36864
#define QKV_WL 64512
#define QKV_SMEM 92160

__global__ __launch_bounds__(256, 1) void qkv_mma(
    const float* __restrict__ x,
    const float* __restrict__ Wq,
    const float* __restrict__ Wk,
    const float* __restrict__ Wv)
{
    extern __shared__ __align__(16) char sm[];
    char* Xh = sm + QKV_XH;
    char* Xl = sm + QKV_XL;
    char* Wh = sm + QKV_WH;
    char* Wl = sm + QKV_WL;

    const int tid = threadIdx.x;
    const int wid = tid >> 5;
    const int lane = tid & 31;
    const int g  = lane >> 2;
    const int t3 = lane & 3;
    const int rowblk = blockIdx.x * 128;

    float c[24][4];
    #pragma unroll
    for (int nt = 0; nt < 24; nt++)
        #pragma unroll
        for (int i = 0; i < 4; i++) c[nt][i] = 0.f;

    for (int kc = 0; kc < NE; kc += 64) {
        __syncthreads();
        {
            const int r  = tid >> 1;
            const int c0 = (tid & 1) * 32;
            const float4* src = (const float4*)&x[(size_t)(rowblk + r) * NE + kc + c0];
            uint32_t hp[16], lp[16];
            #pragma unroll
            for (int i = 0; i < 8; i++) {
                float4 v = src[i];
                split2(v.x, v.y, hp[2*i],   lp[2*i]);
                split2(v.z, v.w, hp[2*i+1], lp[2*i+1]);
            }
            const int ob = r * ROWB + c0 * 2;
            #pragma unroll
            for (int i = 0; i < 4; i++) {
                *(uint4*)(Xh + ob + 16*i) = make_uint4(hp[4*i], hp[4*i+1], hp[4*i+2], hp[4*i+3]);
                *(uint4*)(Xl + ob + 16*i) = make_uint4(lp[4*i], lp[4*i+1], lp[4*i+2], lp[4*i+3]);
            }
        }
        if (tid < 192) {
            const float* Wsel = (tid < 64) ? Wq : ((tid < 128) ? Wk : Wv);
            const int wr = tid & 63;
            const float4* src = (const float4*)&Wsel[(size_t)wr * NE + kc];
            uint32_t hp[32], lp[32];
            #pragma unroll
            for (int i = 0; i < 16; i++) {
                float4 v = src[i];
                split2(v.x, v.y, hp[2*i],   lp[2*i]);
                split2(v.z, v.w, hp[2*i+1], lp[2*i+1]);
            }
            const int ob = tid * ROWB;
            #pragma unroll
            for (int i = 0; i < 8; i++) {
                *(uint4*)(Wh + ob + 16*i) = make_uint4(hp[4*i], hp[4*i+1], hp[4*i+2], hp[4*i+3]);
                *(uint4*)(Wl + ob + 16*i) = make_uint4(lp[4*i], lp[4*i+1], lp[4*i+2], lp[4*i+3]);
            }
        }
        __syncthreads();

        const int rb = (wid * 16 + g) * ROWB;
        #pragma unroll
        for (int ks = 0; ks < 4; ks++) {
            const int colb = ks * 32 + t3 * 4;
            uint32_t ah[4], al[4];
            ah[0] = *(uint32_t*)(Xh + rb + colb);
            ah[1] = *(uint32_t*)(Xh + rb + 8*ROWB + colb);
            ah[2] = *(uint32_t*)(Xh + rb + colb + 16);
            ah[3] = *(uint32_t*)(Xh + rb + 8*ROWB + colb + 16);
            al[0] = *(uint32_t*)(Xl + rb + colb);
            al[1] = *(uint32_t*)(Xl + rb + 8*ROWB + colb);
            al[2] = *(uint32_t*)(Xl + rb + colb + 16);
            al[3] = *(uint32_t*)(Xl + rb + 8*ROWB + colb + 16);
            #pragma unroll
            for (int nt = 0; nt < 24; nt++) {
                const int ab = (nt * 8 + g) * ROWB + colb;
                uint32_t bh0 = *(uint32_t*)(Wh + ab);
                uint32_t bh1 = *(uint32_t*)(Wh + ab + 16);
                uint32_t bl0 = *(uint32_t*)(Wl + ab);
                uint32_t bl1 = *(uint32_t*)(Wl + ab + 16);
                mma16816(c[nt], ah, bh0, bh1);
                mma16816(c[nt], ah, bl0, bl1);
                mma16816(c[nt], al, bh0, bh1);
            }
        }
    }

    const int r0 = rowblk + wid * 16 + g;
    // Q: fp32
    #pragma unroll
    for (int nt = 0; nt < 8; nt++) {
        const int col = nt * 8 + t3 * 2;
        *(float2*)&g_q[(size_t)r0 * HS + col]       = make_float2(c[nt][0], c[nt][1]);
        *(float2*)&g_q[(size_t)(r0 + 8) * HS + col] = make_float2(c[nt][2], c[nt][3]);
    }
    // K: split bf16 pairs along d
    #pragma unroll
    for (int nt = 8; nt < 16; nt++) {
        const int pidx = (nt - 8) * 4 + t3;
        uint32_t hi, lo;
        split2(c[nt][0], c[nt][1], hi, lo);
        g_khp[(size_t)r0 * 32 + pidx] = hi;
        g_klp[(size_t)r0 * 32 + pidx] = lo;
        split2(c[nt][2], c[nt][3], hi, lo);
        g_khp[(size_t)(r0 + 8) * 32 + pidx] = hi;
        g_klp[(size_t)(r0 + 8) * 32 + pidx] = lo;
    }

    // V: stage fp32 to smem, then split + write transposed coalesced
    __syncthreads();
    float* Vs = (float*)sm;       // [64][132]
    const int rloc = wid * 16 + g;
    #pragma unroll
    for (int nt = 16; nt < 24; nt++) {
        const int n = nt * 8 + t3 * 2 - 128;
        Vs[n * 132 + rloc]           = c[nt][0];
        Vs[(n + 1) * 132 + rloc]     = c[nt][1];
        Vs[n * 132 + rloc + 8]       = c[nt][2];
        Vs[(n + 1) * 132 + rloc + 8] = c[nt][3];
    }
    __syncthreads();
    {
        const int d  = tid >> 2;
        const int cc = (tid & 3) * 32;
        const int bb = rowblk >> 12;
        const int t0 = rowblk & (NT - 1);
        uint32_t* dh = &g_vthp[((size_t)(bb * HS + d)) * 2048 + (t0 + cc) / 2];
        uint32_t* dl = &g_vtlp[((size_t)(bb * HS + d)) * 2048 + (t0 + cc) / 2];
        #pragma unroll
        for (int i = 0; i < 8; i++) {
            float4 v = *(float4*)&Vs[d * 132 + cc + 4*i];
            uint32_t h0, l0, h1, l1;
            split2(v.x, v.y, h0, l0);
            split2(v.z, v.w, h1, l1);
            dh[2*i] = h0;  dh[2*i+1] = h1;
            dl[2*i] = l0;  dl[2*i+1] = l1;
        }
    }
}

// ===========================================================================
// Stage 2: causal flash attention. 64-row Q tiles, paired (qt, 63-qt).
// Warps 0-3: keys 0-31 of each kv tile; warps 4-7: keys 32-63.
// cp.async double-buffered K/V (precomputed bf16 hi/lo), ldmatrix fragments.
// ===========================================================================
#define STGB 36864              // one stage: KH,KL,VH,VL @ 9216 each
#define AT_QHO 73728
#define AT_QLO 82944
#define AT_MSO 92160            // float2[2][64]
#define AT_SMEM 93184
#define OEXW 66                 // O-exchange row stride (floats)

__global__ __launch_bounds__(256, 1) void attn2(float* __restrict__ o)
{
    extern __shared__ __align__(16) char sm[];
    const uint32_t sb = smem_u32(sm);
    const int tid  = threadIdx.x;
    const int wid  = tid >> 5;
    const int lane = tid & 31;
    const int g    = lane >> 2;
    const int t3   = lane & 3;
    const int wq   = wid & 3;         // row-group within tile
    const int side = wid >> 2;        // key-half
    const int b    = blockIdx.y;

    // ldmatrix per-lane address offsets
    const int m8 = lane >> 3;         // matrix id 0..3
    const int r8 = lane & 7;
    const uint32_t lmk = (uint32_t)((side * 32 + (m8 >> 1) * 8 + r8) * ROWB + (m8 & 1) * 16);
    const uint32_t lmv = (uint32_t)(((m8 >> 1) * 8 + r8) * ROWB + (m8 & 1) * 16 + side * 64);

    const char* kh_base = (const char*)g_khp + (size_t)b * NT * 128;
    const char* kl_base = (const char*)g_klp + (size_t)b * NT * 128;
    const char* vh_base = (const char*)g_vthp + (size_t)b * HS * 8192;
    const char* vl_base = (const char*)g_vtlp + (size_t)b * HS * 8192;

    // prefetch-chunk mapping (per thread: 2 consecutive 16B chunks per buffer)
    const int pc_row = (tid * 2) >> 3;         // 0..63
    const int pc_off = ((tid * 2) & 7) * 16;   // 0,32,64,96

    for (int half = 0; half < 2; half++) {
        const int qt = half ? (63 - (int)blockIdx.x) : (int)blockIdx.x;
        const int nkt = qt + 1;
        const int qrow = b * NT + qt * 64;

        __syncthreads();
        // ---- stage Q (scaled 1/8, split) ----
        {
            const int r  = tid >> 2;
            const int c0 = (tid & 3) * 16;
            const float4* src = (const float4*)&g_q[(size_t)(qrow + r) * HS + c0];
            uint32_t hp[8], lp[8];
            #pragma unroll
            for (int i = 0; i < 4; i++) {
                float4 v = src[i];
                split2(v.x * 0.125f, v.y * 0.125f, hp[2*i],   lp[2*i]);
                split2(v.z * 0.125f, v.w * 0.125f, hp[2*i+1], lp[2*i+1]);
            }
            const int ob = r * ROWB + c0 * 2;
            *(uint4*)(sm + AT_QHO + ob)      = make_uint4(hp[0], hp[1], hp[2], hp[3]);
            *(uint4*)(sm + AT_QHO + ob + 16) = make_uint4(hp[4], hp[5], hp[6], hp[7]);
            *(uint4*)(sm + AT_QLO + ob)      = make_uint4(lp[0], lp[1], lp[2], lp[3]);
            *(uint4*)(sm + AT_QLO + ob + 16) = make_uint4(lp[4], lp[5], lp[6], lp[7]);
        }
        __syncthreads();

        // ---- preload Q fragments (rows wq*16+g, +8) ----
        uint32_t qh[4][4], ql[4][4];
        {
            const int rb = (wq * 16 + g) * ROWB;
            #pragma unroll
            for (int ks = 0; ks < 4; ks++) {
                const int colb = ks * 32 + t3 * 4;
                qh[ks][0] = *(uint32_t*)(sm + AT_QHO + rb + colb);
                qh[ks][1] = *(uint32_t*)(sm + AT_QHO + rb + 8*ROWB + colb);
                qh[ks][2] = *(uint32_t*)(sm + AT_QHO + rb + colb + 16);
                qh[ks][3] = *(uint32_t*)(sm + AT_QHO + rb + 8*ROWB + colb + 16);
                ql[ks][0] = *(uint32_t*)(sm + AT_QLO + rb + colb);
                ql[ks][1] = *(uint32_t*)(sm + AT_QLO + rb + 8*ROWB + colb);
                ql[ks][2] = *(uint32_t*)(sm + AT_QLO + rb + colb + 16);
                ql[ks][3] = *(uint32_t*)(sm + AT_QLO + rb + 8*ROWB + colb + 16);
            }
        }

        float oacc[8][4];
        #pragma unroll
        for (int nt = 0; nt < 8; nt++)
            #pragma unroll
            for (int i = 0; i < 4; i++) oacc[nt][i] = 0.f;
        float mi0 = -1e30f, mi1 = -1e30f, li0 = 0.f, li1 = 0.f;

        // ---- prefetch tile 0 ----
        {
            const uint32_t so = sb + pc_row * ROWB + pc_off;
            const size_t ko = (size_t)(pc_row) * 128 + pc_off;
            const size_t vo = (size_t)pc_row * 8192 + pc_off;
            cp16(so,                kh_base + ko);  cp16(so + 16,                kh_base + ko + 16);
            cp16(so + 9216,         kl_base + ko);  cp16(so + 9216 + 16,         kl_base + ko + 16);
            cp16(so + 18432,        vh_base + vo);  cp16(so + 18432 + 16,        vh_base + vo + 16);
            cp16(so + 27648,        vl_base + vo);  cp16(so + 27648 + 16,        vl_base + vo + 16);
            asm volatile("cp.async.commit_group;" ::: "memory");
        }

        for (int kt = 0; kt < nkt; kt++) {
            if (kt + 1 < nkt) {
                const int st = (kt + 1) & 1;
                const uint32_t so = sb + st * STGB + pc_row * ROWB + pc_off;
                const size_t ko = (size_t)((kt + 1) * 64 + pc_row) * 128 + pc_off;
                const size_t vo = (size_t)pc_row * 8192 + (kt + 1) * 128 + pc_off;
                cp16(so,         kh_base + ko);  cp16(so + 16,         kh_base + ko + 16);
                cp16(so + 9216,  kl_base + ko);  cp16(so + 9216 + 16,  kl_base + ko + 16);
                cp16(so + 18432, vh_base + vo);  cp16(so + 18432 + 16, vh_base + vo + 16);
                cp16(so + 27648, vl_base + vo);  cp16(so + 27648 + 16, vl_base + vo + 16);
                asm volatile("cp.async.commit_group;" ::: "memory");
                asm volatile("cp.async.wait_group 1;" ::: "memory");
            } else {
                asm volatile("cp.async.wait_group 0;" ::: "memory");
            }
            __syncthreads();

            const uint32_t khb = sb + (kt & 1) * STGB;
            const uint32_t klb = khb + 9216;
            const uint32_t vhb = khb + 18432;
            const uint32_t vlb = khb + 27648;

            // ---- S = Q K^T (warp's 32 keys) ----
            float s[4][4];
            #pragma unroll
            for (int nt = 0; nt < 4; nt++)
                #pragma unroll
                for (int i = 0; i < 4; i++) s[nt][i] = 0.f;
            #pragma unroll
            for (int ks = 0; ks < 4; ks++) {
                uint32_t a4[4], b4[4], c4[4], d4[4];
                ldsm4(a4, khb + lmk + ks * 32);
                ldsm4(b4, khb + lmk + 16 * ROWB + ks * 32);
                ldsm4(c4, klb + lmk + ks * 32);
                ldsm4(d4, klb + lmk + 16 * ROWB + ks * 32);
                mma16816(s[0], qh[ks], a4[0], a4[1]);
                mma16816(s[0], qh[ks], c4[0], c4[1]);
                mma16816(s[0], ql[ks], a4[0], a4[1]);
                mma16816(s[1], qh[ks], a4[2], a4[3]);
                mma16816(s[1], qh[ks], c4[2], c4[3]);
                mma16816(s[1], ql[ks], a4[2], a4[3]);
                mma16816(s[2], qh[ks], b4[0], b4[1]);
                mma16816(s[2], qh[ks], d4[0], d4[1]);
                mma16816(s[2], ql[ks], b4[0], b4[1]);
                mma16816(s[3], qh[ks], b4[2], b4[3]);
                mma16816(s[3], qh[ks], d4[2], d4[3]);
                mma16816(s[3], ql[ks], b4[2], b4[3]);
            }

            // ---- causal mask (diag tile only) ----
            if (kt == qt) {
                const int lr0 = wq * 16 + g;
                #pragma unroll
                for (int nt = 0; nt < 4; nt++) {
                    const int lc = side * 32 + nt * 8 + t3 * 2;
                    if (lc > lr0)         s[nt][0] = -1e30f;
                    if (lc + 1 > lr0)     s[nt][1] = -1e30f;
                    if (lc > lr0 + 8)     s[nt][2] = -1e30f;
                    if (lc + 1 > lr0 + 8) s[nt][3] = -1e30f;
                }
            }

            // ---- partial softmax over warp's 32 cols ----
            float m0 = -1e30f, m1 = -1e30f;
            #pragma unroll
            for (int nt = 0; nt < 4; nt++) {
                m0 = fmaxf(m0, fmaxf(s[nt][0], s[nt][1]));
                m1 = fmaxf(m1, fmaxf(s[nt][2], s[nt][3]));
            }
            m0 = fmaxf(m0, __shfl_xor_sync(0xffffffffu, m0, 1));
            m0 = fmaxf(m0, __shfl_xor_sync(0xffffffffu, m0, 2));
            m1 = fmaxf(m1, __shfl_xor_sync(0xffffffffu, m1, 1));
            m1 = fmaxf(m1, __shfl_xor_sync(0xffffffffu, m1, 2));

            float sum0 = 0.f, sum1 = 0.f;
            #pragma unroll
            for (int nt = 0; nt < 4; nt++) {
                s[nt][0] = __expf(s[nt][0] - m0);
                s[nt][1] = __expf(s[nt][1] - m0);
                s[nt][2] = __expf(s[nt][2] - m1);
                s[nt][3] = __expf(s[nt][3] - m1);
                sum0 += s[nt][0] + s[nt][1];
                sum1 += s[nt][2] + s[nt][3];
            }
            sum0 += __shfl_xor_sync(0xffffffffu, sum0, 1);
            sum0 += __shfl_xor_sync(0xffffffffu, sum0, 2);
            sum1 += __shfl_xor_sync(0xffffffffu, sum1, 1);
            sum1 += __shfl_xor_sync(0xffffffffu, sum1, 2);

            // ---- exchange (max, sum) with partner warp ----
            if (t3 == 0) {
                *(float2*)(sm + AT_MSO + (side * 64 + wq * 16 + g) * 8)     = make_float2(m0, sum0);
                *(float2*)(sm + AT_MSO + (side * 64 + wq * 16 + g + 8) * 8) = make_float2(m1, sum1);
            }
            __syncthreads();
            const float2 ot0 = *(float2*)(sm + AT_MSO + ((1 - side) * 64 + wq * 16 + g) * 8);
            const float2 ot1 = *(float2*)(sm + AT_MSO + ((1 - side) * 64 + wq * 16 + g + 8) * 8);

            const float mn0 = fmaxf(mi0, fmaxf(m0, ot0.x));
            const float mn1 = fmaxf(mi1, fmaxf(m1, ot1.x));
            const float fo0 = __expf(m0 - mn0), fo1 = __expf(m1 - mn1);
            const float ft0 = __expf(ot0.x - mn0), ft1 = __expf(ot1.x - mn1);
            const float corr0 = __expf(mi0 - mn0), corr1 = __expf(mi1 - mn1);
            li0 = li0 * corr0 + sum0 * fo0 + ot0.y * ft0;
            li1 = li1 * corr1 + sum1 * fo1 + ot1.y * ft1;
            mi0 = mn0;  mi1 = mn1;

            #pragma unroll
            for (int nt = 0; nt < 4; nt++) {
                s[nt][0] *= fo0;  s[nt][1] *= fo0;
                s[nt][2] *= fo1;  s[nt][3] *= fo1;
            }
            #pragma unroll
            for (int nt = 0; nt < 8; nt++) {
                oacc[nt][0] *= corr0;  oacc[nt][1] *= corr0;
                oacc[nt][2] *= corr1;  oacc[nt][3] *= corr1;
            }

            // ---- O += P V (warp's 32 keys over all 64 d) ----
            #pragma unroll
            for (int k2 = 0; k2 < 2; k2++) {
                uint32_t pah[4], pal[4];
                split2(s[2*k2][0],   s[2*k2][1],   pah[0], pal[0]);
                split2(s[2*k2][2],   s[2*k2][3],   pah[1], pal[1]);
                split2(s[2*k2+1][0], s[2*k2+1][1], pah[2], pal[2]);
                split2(s[2*k2+1][2], s[2*k2+1][3], pah[3], pal[3]);
                #pragma unroll
                for (int dt = 0; dt < 4; dt++) {
                    uint32_t vh4[4], vl4[4];
                    ldsm4(vh4, vhb + dt * (16 * ROWB) + lmv + k2 * 32);
                    ldsm4(vl4, vlb + dt * (16 * ROWB) + lmv + k2 * 32);
                    mma16816(oacc[2*dt],   pah, vh4[0], vh4[1]);
                    mma16816(oacc[2*dt],   pah, vl4[0], vl4[1]);
                    mma16816(oacc[2*dt],   pal, vh4[0], vh4[1]);
                    mma16816(oacc[2*dt+1], pah, vh4[2], vh4[3]);
                    mma16816(oacc[2*dt+1], pah, vl4[2], vl4[3]);
                    mma16816(oacc[2*dt+1], pal, vh4[2], vh4[3]);
                }
            }
            __syncthreads();
        }

        // ---- epilogue: merge O partials across warp pairs, store ----
        float* Oex = (float*)sm;   // alias stage 0 (pipeline drained)
        if (side == 1) {
            #pragma unroll
            for (int nt = 0; nt < 8; nt++) {
                const int col = nt * 8 + t3 * 2;
                Oex[(wq*16 + g) * OEXW + col]         = oacc[nt][0];
                Oex[(wq*16 + g) * OEXW + col + 1]     = oacc[nt][1];
                Oex[(wq*16 + g + 8) * OEXW + col]     = oacc[nt][2];
                Oex[(wq*16 + g + 8) * OEXW + col + 1] = oacc[nt][3];
            }
        }
        __syncthreads();
        if (side == 0) {
            const float inv0 = 1.0f / li0;
            const float inv1 = 1.0f / li1;
            const int rowA = qrow + wq * 16 + g;
            #pragma unroll
            for (int nt = 0; nt < 8; nt++) {
                const int col = nt * 8 + t3 * 2;
                float a0 = (oacc[nt][0] + Oex[(wq*16 + g) * OEXW + col])     * inv0;
                float a1 = (oacc[nt][1] + Oex[(wq*16 + g) * OEXW + col + 1]) * inv0;
                float a2 = (oacc[nt][2] + Oex[(wq*16 + g + 8) * OEXW + col])     * inv1;
                float a3 = (oacc[nt][3] + Oex[(wq*16 + g + 8) * OEXW + col + 1]) * inv1;
                *(float2*)&o[(size_t)rowA * HS + col]       = make_float2(a0, a1);
                *(float2*)&o[(size_t)(rowA + 8) * HS + col] = make_float2(a2, a3);
            }
        }
    }
}

// ===========================================================================
extern "C" void kernel_launch(void* const* d_in, const int* in_sizes, int n_in,
                              void* d_out, int out_size)
{
    const float* x  = (const float*)d_in[0];
    const float* Wq = (const float*)d_in[1];
    const float* Wk = (const float*)d_in[2];
    const float* Wv = (const float*)d_in[3];
    float* out = (float*)d_out;
    (void)in_sizes; (void)n_in; (void)out_size;

    cudaFuncSetAttribute(qkv_mma, cudaFuncAttributeMaxDynamicSharedMemorySize,
                         QKV_SMEM);
    qkv_mma<<<128, 256, QKV_SMEM>>>(x, Wq, Wk, Wv);

    cudaFuncSetAttribute(attn2, cudaFuncAttributeMaxDynamicSharedMemorySize,
                         AT_SMEM);
    attn2<<<dim3(32, NB), 256, AT_SMEM>>>(out);
}

// round 6
// speedup vs baseline: 3.7518x; 1.1468x over previous
#include <cuda_runtime.h>
#include <cuda_bf16.h>
#include <cstdint>

#define NB 4
#define NT 4096
#define NE 1024
#define HS 64

// Scratch (static device arrays — no allocation)
__device__ float    g_q[NB * NT * HS];
__device__ uint32_t g_khp[NB * NT * 32];     // K hi, bf16x2 pairs along d
__device__ uint32_t g_klp[NB * NT * 32];     // K lo
__device__ uint32_t g_vthp[NB * HS * 2048];  // V^T hi, [b][d][t-pairs]
__device__ uint32_t g_vtlp[NB * HS * 2048];  // V^T lo
__device__ uint32_t g_whp[192 * 512];        // W split hi: rows q|k|v, bf16x2 pairs
__device__ uint32_t g_wlp[192 * 512];        // W split lo

// ---------------------------------------------------------------------------
// Helpers
// ---------------------------------------------------------------------------
__device__ __forceinline__ void split2(float a, float b, uint32_t& hi, uint32_t& lo) {
    __nv_bfloat162 h2 = __floats2bfloat162_rn(a, b);
    float2 hf = __bfloat1622float2(h2);
    __nv_bfloat162 l2 = __floats2bfloat162_rn(a - hf.x, b - hf.y);
    hi = *reinterpret_cast<uint32_t*>(&h2);
    lo = *reinterpret_cast<uint32_t*>(&l2);
}

__device__ __forceinline__ void mma16816(float* c, const uint32_t* a,
                                         uint32_t b0, uint32_t b1) {
    asm volatile(
        "mma.sync.aligned.m16n8k16.row.col.f32.bf16.bf16.f32 "
        "{%0,%1,%2,%3}, {%4,%5,%6,%7}, {%8,%9}, {%0,%1,%2,%3};"
        : "+f"(c[0]), "+f"(c[1]), "+f"(c[2]), "+f"(c[3])
        : "r"(a[0]), "r"(a[1]), "r"(a[2]), "r"(a[3]), "r"(b0), "r"(b1));
}

__device__ __forceinline__ void ldsm4(uint32_t* r, uint32_t addr) {
    asm volatile("ldmatrix.sync.aligned.m8n8.x4.shared.b16 {%0,%1,%2,%3}, [%4];"
                 : "=r"(r[0]), "=r"(r[1]), "=r"(r[2]), "=r"(r[3]) : "r"(addr));
}

__device__ __forceinline__ uint32_t smem_u32(const void* p) {
    uint32_t a;
    asm("{ .reg .u64 t; cvta.to.shared.u64 t, %1; cvt.u32.u64 %0, t; }"
        : "=r"(a) : "l"(p));
    return a;
}

__device__ __forceinline__ void cp16(uint32_t s, const void* g) {
    asm volatile("cp.async.cg.shared.global [%0], [%1], 16;"
                 :: "r"(s), "l"(__cvta_generic_to_global(g)) : "memory");
}

#define ROWB 144   // padded smem row stride — conflict-free ldmatrix

// ===========================================================================
// Stage 0: one-time W split (fp32 -> bf16 hi/lo), rows: q 0-63 | k 64-127 | v 128-191
// ===========================================================================
__global__ __launch_bounds__(256) void wprep(
    const float* __restrict__ Wq,
    const float* __restrict__ Wk,
    const float* __restrict__ Wv)
{
    const int row = blockIdx.x;                 // 0..191
    const float* W = (row < 64) ? Wq : ((row < 128) ? Wk : Wv);
    const int r = row & 63;
    #pragma unroll
    for (int i = 0; i < 2; i++) {
        const int p = threadIdx.x + i * 256;    // pair index 0..511
        float2 v = *(const float2*)&W[(size_t)r * NE + 2 * p];
        uint32_t hi, lo;
        split2(v.x, v.y, hi, lo);
        g_whp[row * 512 + p] = hi;
        g_wlp[row * 512 + p] = lo;
    }
}

// ===========================================================================
// Stage 1: fused QKV projection. W via cp.async (preconverted), X warp-local.
// ===========================================================================
#define QKV_XH 0
#define QKV_XL 18432          // 128*144
#define QKV_W0 36864          // stage 0: Wh | Wl (27648 each)
#define QKV_W1 92160          // stage 1
#define QKV_WSTG 55296
#define QKV_SMEM 147456

__global__ __launch_bounds__(256, 1) void qkv_mma(
    const float* __restrict__ x,
    const float* __restrict__ Wq,
    const float* __restrict__ Wk,
    const float* __restrict__ Wv)
{
    extern __shared__ __align__(16) char sm[];
    const uint32_t sb = smem_u32(sm);
    char* Xh = sm + QKV_XH;
    char* Xl = sm + QKV_XL;

    const int tid = threadIdx.x;
    const int wid = tid >> 5;
    const int lane = tid & 31;
    const int g  = lane >> 2;
    const int t3 = lane & 3;
    const int m8 = lane >> 3;
    const int r8 = lane & 7;
    const int rowblk = blockIdx.x * 128;

    const uint32_t lmw = (uint32_t)(((m8 >> 1) * 8 + r8) * ROWB + (m8 & 1) * 16);

    // X load mapping (warp-local rows)
    const int xrow = tid >> 1;
    const int xc0  = (tid & 1) * 32;
    const float4* xsrc0 = (const float4*)&x[(size_t)(rowblk + xrow) * NE + xc0];

    float c[24][4];
    #pragma unroll
    for (int nt = 0; nt < 24; nt++)
        #pragma unroll
        for (int i = 0; i < 4; i++) c[nt][i] = 0.f;

    // ---- preload X chunk 0 into regs ----
    float4 xr[8];
    #pragma unroll
    for (int i = 0; i < 8; i++) xr[i] = xsrc0[i];

    // ---- prefetch W chunk 0 into stage 0 ----
    {
        const uint32_t wst = sb + QKV_W0;
        #pragma unroll
        for (int i = 0; i < 6; i++) {
            const int idx = tid + i * 256;       // 0..1535
            const int row = idx >> 3;
            const int off = (idx & 7) * 16;
            cp16(wst + row * ROWB + off,         (const char*)g_whp + row * 2048 + off);
            cp16(wst + 27648 + row * ROWB + off, (const char*)g_wlp + row * 2048 + off);
        }
        asm volatile("cp.async.commit_group;" ::: "memory");
    }

    const int xob = xrow * ROWB + xc0 * 2;

    for (int kci = 0; kci < 16; kci++) {
        __syncthreads();   // stage (kci+1)&1 free of readers (MMAs of kci-1 done)

        // prefetch next W chunk
        if (kci + 1 < 16) {
            const uint32_t wst = sb + ((kci + 1) & 1 ? QKV_W1 : QKV_W0);
            const int kb2 = (kci + 1) * 128;     // byte offset within W row (kc*2)
            #pragma unroll
            for (int i = 0; i < 6; i++) {
                const int idx = tid + i * 256;
                const int row = idx >> 3;
                const int off = (idx & 7) * 16;
                cp16(wst + row * ROWB + off,         (const char*)g_whp + row * 2048 + kb2 + off);
                cp16(wst + 27648 + row * ROWB + off, (const char*)g_wlp + row * 2048 + kb2 + off);
            }
            asm volatile("cp.async.commit_group;" ::: "memory");
        }

        // split current X regs into warp-local smem
        {
            uint32_t hp[16], lp[16];
            #pragma unroll
            for (int i = 0; i < 8; i++) {
                split2(xr[i].x, xr[i].y, hp[2*i],   lp[2*i]);
                split2(xr[i].z, xr[i].w, hp[2*i+1], lp[2*i+1]);
            }
            #pragma unroll
            for (int i = 0; i < 4; i++) {
                *(uint4*)(Xh + xob + 16*i) = make_uint4(hp[4*i], hp[4*i+1], hp[4*i+2], hp[4*i+3]);
                *(uint4*)(Xl + xob + 16*i) = make_uint4(lp[4*i], lp[4*i+1], lp[4*i+2], lp[4*i+3]);
            }
        }
        __syncwarp();

        // issue next X loads (latency hides behind MMA loop)
        if (kci + 1 < 16) {
            const float4* xsrc = (const float4*)&x[(size_t)(rowblk + xrow) * NE + (kci + 1) * 64 + xc0];
            #pragma unroll
            for (int i = 0; i < 8; i++) xr[i] = xsrc[i];
        }

        if (kci + 1 < 16)
            asm volatile("cp.async.wait_group 1;" ::: "memory");
        else
            asm volatile("cp.async.wait_group 0;" ::: "memory");
        __syncthreads();   // W stage for kci visible to all

        const uint32_t whb = sb + ((kci & 1) ? QKV_W1 : QKV_W0);
        const uint32_t wlb = whb + 27648;

        const int rb = (wid * 16 + g) * ROWB;
        #pragma unroll
        for (int ks = 0; ks < 4; ks++) {
            const int colb = ks * 32 + t3 * 4;
            uint32_t ah[4], al[4];
            ah[0] = *(uint32_t*)(Xh + rb + colb);
            ah[1] = *(uint32_t*)(Xh + rb + 8*ROWB + colb);
            ah[2] = *(uint32_t*)(Xh + rb + colb + 16);
            ah[3] = *(uint32_t*)(Xh + rb + 8*ROWB + colb + 16);
            al[0] = *(uint32_t*)(Xl + rb + colb);
            al[1] = *(uint32_t*)(Xl + rb + 8*ROWB + colb);
            al[2] = *(uint32_t*)(Xl + rb + colb + 16);
            al[3] = *(uint32_t*)(Xl + rb + 8*ROWB + colb + 16);
            #pragma unroll
            for (int ntp = 0; ntp < 12; ntp++) {
                uint32_t wh4[4], wl4[4];
                ldsm4(wh4, whb + lmw + ntp * (16 * ROWB) + ks * 32);
                ldsm4(wl4, wlb + lmw + ntp * (16 * ROWB) + ks * 32);
                mma16816(c[2*ntp],   ah, wh4[0], wh4[1]);
                mma16816(c[2*ntp],   ah, wl4[0], wl4[1]);
                mma16816(c[2*ntp],   al, wh4[0], wh4[1]);
                mma16816(c[2*ntp+1], ah, wh4[2], wh4[3]);
                mma16816(c[2*ntp+1], ah, wl4[2], wl4[3]);
                mma16816(c[2*ntp+1], al, wh4[2], wh4[3]);
            }
        }
    }

    const int r0 = rowblk + wid * 16 + g;
    // Q: fp32
    #pragma unroll
    for (int nt = 0; nt < 8; nt++) {
        const int col = nt * 8 + t3 * 2;
        *(float2*)&g_q[(size_t)r0 * HS + col]       = make_float2(c[nt][0], c[nt][1]);
        *(float2*)&g_q[(size_t)(r0 + 8) * HS + col] = make_float2(c[nt][2], c[nt][3]);
    }
    // K: split bf16 pairs along d
    #pragma unroll
    for (int nt = 8; nt < 16; nt++) {
        const int pidx = (nt - 8) * 4 + t3;
        uint32_t hi, lo;
        split2(c[nt][0], c[nt][1], hi, lo);
        g_khp[(size_t)r0 * 32 + pidx] = hi;
        g_klp[(size_t)r0 * 32 + pidx] = lo;
        split2(c[nt][2], c[nt][3], hi, lo);
        g_khp[(size_t)(r0 + 8) * 32 + pidx] = hi;
        g_klp[(size_t)(r0 + 8) * 32 + pidx] = lo;
    }

    // V: stage fp32 to smem, then split + write transposed coalesced
    __syncthreads();
    float* Vs = (float*)sm;       // [64][132] — X area, dead now
    const int rloc = wid * 16 + g;
    #pragma unroll
    for (int nt = 16; nt < 24; nt++) {
        const int n = nt * 8 + t3 * 2 - 128;
        Vs[n * 132 + rloc]           = c[nt][0];
        Vs[(n + 1) * 132 + rloc]     = c[nt][1];
        Vs[n * 132 + rloc + 8]       = c[nt][2];
        Vs[(n + 1) * 132 + rloc + 8] = c[nt][3];
    }
    __syncthreads();
    {
        const int d  = tid >> 2;
        const int cc = (tid & 3) * 32;
        const int bb = rowblk >> 12;
        const int t0 = rowblk & (NT - 1);
        uint32_t* dh = &g_vthp[((size_t)(bb * HS + d)) * 2048 + (t0 + cc) / 2];
        uint32_t* dl = &g_vtlp[((size_t)(bb * HS + d)) * 2048 + (t0 + cc) / 2];
        #pragma unroll
        for (int i = 0; i < 8; i++) {
            float4 v = *(float4*)&Vs[d * 132 + cc + 4*i];
            uint32_t h0, l0, h1, l1;
            split2(v.x, v.y, h0, l0);
            split2(v.z, v.w, h1, l1);
            dh[2*i] = h0;  dh[2*i+1] = h1;
            dl[2*i] = l0;  dl[2*i+1] = l1;
        }
    }
}

// ===========================================================================
// Stage 2: causal flash attention (unchanged from R5 — passing, 116.8 us).
// ===========================================================================
#define STGB 36864
#define AT_QHO 73728
#define AT_QLO 82944
#define AT_MSO 92160
#define AT_SMEM 93184
#define OEXW 66

__global__ __launch_bounds__(256, 1) void attn2(float* __restrict__ o)
{
    extern __shared__ __align__(16) char sm[];
    const uint32_t sb = smem_u32(sm);
    const int tid  = threadIdx.x;
    const int wid  = tid >> 5;
    const int lane = tid & 31;
    const int g    = lane >> 2;
    const int t3   = lane & 3;
    const int wq   = wid & 3;
    const int side = wid >> 2;
    const int b    = blockIdx.y;

    const int m8 = lane >> 3;
    const int r8 = lane & 7;
    const uint32_t lmk = (uint32_t)((side * 32 + (m8 >> 1) * 8 + r8) * ROWB + (m8 & 1) * 16);
    const uint32_t lmv = (uint32_t)(((m8 >> 1) * 8 + r8) * ROWB + (m8 & 1) * 16 + side * 64);

    const char* kh_base = (const char*)g_khp + (size_t)b * NT * 128;
    const char* kl_base = (const char*)g_klp + (size_t)b * NT * 128;
    const char* vh_base = (const char*)g_vthp + (size_t)b * HS * 8192;
    const char* vl_base = (const char*)g_vtlp + (size_t)b * HS * 8192;

    const int pc_row = (tid * 2) >> 3;
    const int pc_off = ((tid * 2) & 7) * 16;

    for (int half = 0; half < 2; half++) {
        const int qt = half ? (63 - (int)blockIdx.x) : (int)blockIdx.x;
        const int nkt = qt + 1;
        const int qrow = b * NT + qt * 64;

        __syncthreads();
        {
            const int r  = tid >> 2;
            const int c0 = (tid & 3) * 16;
            const float4* src = (const float4*)&g_q[(size_t)(qrow + r) * HS + c0];
            uint32_t hp[8], lp[8];
            #pragma unroll
            for (int i = 0; i < 4; i++) {
                float4 v = src[i];
                split2(v.x * 0.125f, v.y * 0.125f, hp[2*i],   lp[2*i]);
                split2(v.z * 0.125f, v.w * 0.125f, hp[2*i+1], lp[2*i+1]);
            }
            const int ob = r * ROWB + c0 * 2;
            *(uint4*)(sm + AT_QHO + ob)      = make_uint4(hp[0], hp[1], hp[2], hp[3]);
            *(uint4*)(sm + AT_QHO + ob + 16) = make_uint4(hp[4], hp[5], hp[6], hp[7]);
            *(uint4*)(sm + AT_QLO + ob)      = make_uint4(lp[0], lp[1], lp[2], lp[3]);
            *(uint4*)(sm + AT_QLO + ob + 16) = make_uint4(lp[4], lp[5], lp[6], lp[7]);
        }
        __syncthreads();

        uint32_t qh[4][4], ql[4][4];
        {
            const int rb = (wq * 16 + g) * ROWB;
            #pragma unroll
            for (int ks = 0; ks < 4; ks++) {
                const int colb = ks * 32 + t3 * 4;
                qh[ks][0] = *(uint32_t*)(sm + AT_QHO + rb + colb);
                qh[ks][1] = *(uint32_t*)(sm + AT_QHO + rb + 8*ROWB + colb);
                qh[ks][2] = *(uint32_t*)(sm + AT_QHO + rb + colb + 16);
                qh[ks][3] = *(uint32_t*)(sm + AT_QHO + rb + 8*ROWB + colb + 16);
                ql[ks][0] = *(uint32_t*)(sm + AT_QLO + rb + colb);
                ql[ks][1] = *(uint32_t*)(sm + AT_QLO + rb + 8*ROWB + colb);
                ql[ks][2] = *(uint32_t*)(sm + AT_QLO + rb + colb + 16);
                ql[ks][3] = *(uint32_t*)(sm + AT_QLO + rb + 8*ROWB + colb + 16);
            }
        }

        float oacc[8][4];
        #pragma unroll
        for (int nt = 0; nt < 8; nt++)
            #pragma unroll
            for (int i = 0; i < 4; i++) oacc[nt][i] = 0.f;
        float mi0 = -1e30f, mi1 = -1e30f, li0 = 0.f, li1 = 0.f;

        {
            const uint32_t so = sb + pc_row * ROWB + pc_off;
            const size_t ko = (size_t)(pc_row) * 128 + pc_off;
            const size_t vo = (size_t)pc_row * 8192 + pc_off;
            cp16(so,         kh_base + ko);  cp16(so + 16,         kh_base + ko + 16);
            cp16(so + 9216,  kl_base + ko);  cp16(so + 9216 + 16,  kl_base + ko + 16);
            cp16(so + 18432, vh_base + vo);  cp16(so + 18432 + 16, vh_base + vo + 16);
            cp16(so + 27648, vl_base + vo);  cp16(so + 27648 + 16, vl_base + vo + 16);
            asm volatile("cp.async.commit_group;" ::: "memory");
        }

        for (int kt = 0; kt < nkt; kt++) {
            if (kt + 1 < nkt) {
                const int st = (kt + 1) & 1;
                const uint32_t so = sb + st * STGB + pc_row * ROWB + pc_off;
                const size_t ko = (size_t)((kt + 1) * 64 + pc_row) * 128 + pc_off;
                const size_t vo = (size_t)pc_row * 8192 + (kt + 1) * 128 + pc_off;
                cp16(so,         kh_base + ko);  cp16(so + 16,         kh_base + ko + 16);
                cp16(so + 9216,  kl_base + ko);  cp16(so + 9216 + 16,  kl_base + ko + 16);
                cp16(so + 18432, vh_base + vo);  cp16(so + 18432 + 16, vh_base + vo + 16);
                cp16(so + 27648, vl_base + vo);  cp16(so + 27648 + 16, vl_base + vo + 16);
                asm volatile("cp.async.commit_group;" ::: "memory");
                asm volatile("cp.async.wait_group 1;" ::: "memory");
            } else {
                asm volatile("cp.async.wait_group 0;" ::: "memory");
            }
            __syncthreads();

            const uint32_t khb = sb + (kt & 1) * STGB;
            const uint32_t klb = khb + 9216;
            const uint32_t vhb = khb + 18432;
            const uint32_t vlb = khb + 27648;

            float s[4][4];
            #pragma unroll
            for (int nt = 0; nt < 4; nt++)
                #pragma unroll
                for (int i = 0; i < 4; i++) s[nt][i] = 0.f;
            #pragma unroll
            for (int ks = 0; ks < 4; ks++) {
                uint32_t a4[4], b4[4], c4[4], d4[4];
                ldsm4(a4, khb + lmk + ks * 32);
                ldsm4(b4, khb + lmk + 16 * ROWB + ks * 32);
                ldsm4(c4, klb + lmk + ks * 32);
                ldsm4(d4, klb + lmk + 16 * ROWB + ks * 32);
                mma16816(s[0], qh[ks], a4[0], a4[1]);
                mma16816(s[0], qh[ks], c4[0], c4[1]);
                mma16816(s[0], ql[ks], a4[0], a4[1]);
                mma16816(s[1], qh[ks], a4[2], a4[3]);
                mma16816(s[1], qh[ks], c4[2], c4[3]);
                mma16816(s[1], ql[ks], a4[2], a4[3]);
                mma16816(s[2], qh[ks], b4[0], b4[1]);
                mma16816(s[2], qh[ks], d4[0], d4[1]);
                mma16816(s[2], ql[ks], b4[0], b4[1]);
                mma16816(s[3], qh[ks], b4[2], b4[3]);
                mma16816(s[3], qh[ks], d4[2], d4[3]);
                mma16816(s[3], ql[ks], b4[2], b4[3]);
            }

            if (kt == qt) {
                const int lr0 = wq * 16 + g;
                #pragma unroll
                for (int nt = 0; nt < 4; nt++) {
                    const int lc = side * 32 + nt * 8 + t3 * 2;
                    if (lc > lr0)         s[nt][0] = -1e30f;
                    if (lc + 1 > lr0)     s[nt][1] = -1e30f;
                    if (lc > lr0 + 8)     s[nt][2] = -1e30f;
                    if (lc + 1 > lr0 + 8) s[nt][3] = -1e30f;
                }
            }

            float m0 = -1e30f, m1 = -1e30f;
            #pragma unroll
            for (int nt = 0; nt < 4; nt++) {
                m0 = fmaxf(m0, fmaxf(s[nt][0], s[nt][1]));
                m1 = fmaxf(m1, fmaxf(s[nt][2], s[nt][3]));
            }
            m0 = fmaxf(m0, __shfl_xor_sync(0xffffffffu, m0, 1));
            m0 = fmaxf(m0, __shfl_xor_sync(0xffffffffu, m0, 2));
            m1 = fmaxf(m1, __shfl_xor_sync(0xffffffffu, m1, 1));
            m1 = fmaxf(m1, __shfl_xor_sync(0xffffffffu, m1, 2));

            float sum0 = 0.f, sum1 = 0.f;
            #pragma unroll
            for (int nt = 0; nt < 4; nt++) {
                s[nt][0] = __expf(s[nt][0] - m0);
                s[nt][1] = __expf(s[nt][1] - m0);
                s[nt][2] = __expf(s[nt][2] - m1);
                s[nt][3] = __expf(s[nt][3] - m1);
                sum0 += s[nt][0] + s[nt][1];
                sum1 += s[nt][2] + s[nt][3];
            }
            sum0 += __shfl_xor_sync(0xffffffffu, sum0, 1);
            sum0 += __shfl_xor_sync(0xffffffffu, sum0, 2);
            sum1 += __shfl_xor_sync(0xffffffffu, sum1, 1);
            sum1 += __shfl_xor_sync(0xffffffffu, sum1, 2);

            if (t3 == 0) {
                *(float2*)(sm + AT_MSO + (side * 64 + wq * 16 + g) * 8)     = make_float2(m0, sum0);
                *(float2*)(sm + AT_MSO + (side * 64 + wq * 16 + g + 8) * 8) = make_float2(m1, sum1);
            }
            __syncthreads();
            const float2 ot0 = *(float2*)(sm + AT_MSO + ((1 - side) * 64 + wq * 16 + g) * 8);
            const float2 ot1 = *(float2*)(sm + AT_MSO + ((1 - side) * 64 + wq * 16 + g + 8) * 8);

            const float mn0 = fmaxf(mi0, fmaxf(m0, ot0.x));
            const float mn1 = fmaxf(mi1, fmaxf(m1, ot1.x));
            const float fo0 = __expf(m0 - mn0), fo1 = __expf(m1 - mn1);
            const float corr0 = __expf(mi0 - mn0), corr1 = __expf(mi1 - mn1);
            li0 = li0 * corr0 + sum0 * fo0 + ot0.y * __expf(ot0.x - mn0);
            li1 = li1 * corr1 + sum1 * fo1 + ot1.y * __expf(ot1.x - mn1);
            mi0 = mn0;  mi1 = mn1;

            #pragma unroll
            for (int nt = 0; nt < 4; nt++) {
                s[nt][0] *= fo0;  s[nt][1] *= fo0;
                s[nt][2] *= fo1;  s[nt][3] *= fo1;
            }
            #pragma unroll
            for (int nt = 0; nt < 8; nt++) {
                oacc[nt][0] *= corr0;  oacc[nt][1] *= corr0;
                oacc[nt][2] *= corr1;  oacc[nt][3] *= corr1;
            }

            #pragma unroll
            for (int k2 = 0; k2 < 2; k2++) {
                uint32_t pah[4], pal[4];
                split2(s[2*k2][0],   s[2*k2][1],   pah[0], pal[0]);
                split2(s[2*k2][2],   s[2*k2][3],   pah[1], pal[1]);
                split2(s[2*k2+1][0], s[2*k2+1][1], pah[2], pal[2]);
                split2(s[2*k2+1][2], s[2*k2+1][3], pah[3], pal[3]);
                #pragma unroll
                for (int dt = 0; dt < 4; dt++) {
                    uint32_t vh4[4], vl4[4];
                    ldsm4(vh4, vhb + dt * (16 * ROWB) + lmv + k2 * 32);
                    ldsm4(vl4, vlb + dt * (16 * ROWB) + lmv + k2 * 32);
                    mma16816(oacc[2*dt],   pah, vh4[0], vh4[1]);
                    mma16816(oacc[2*dt],   pah, vl4[0], vl4[1]);
                    mma16816(oacc[2*dt],   pal, vh4[0], vh4[1]);
                    mma16816(oacc[2*dt+1], pah, vh4[2], vh4[3]);
                    mma16816(oacc[2*dt+1], pah, vl4[2], vl4[3]);
                    mma16816(oacc[2*dt+1], pal, vh4[2], vh4[3]);
                }
            }
            __syncthreads();
        }

        float* Oex = (float*)sm;
        if (side == 1) {
            #pragma unroll
            for (int nt = 0; nt < 8; nt++) {
                const int col = nt * 8 + t3 * 2;
                Oex[(wq*16 + g) * OEXW + col]         = oacc[nt][0];
                Oex[(wq*16 + g) * OEXW + col + 1]     = oacc[nt][1];
                Oex[(wq*16 + g + 8) * OEXW + col]     = oacc[nt][2];
                Oex[(wq*16 + g + 8) * OEXW + col + 1] = oacc[nt][3];
            }
        }
        __syncthreads();
        if (side == 0) {
            const float inv0 = 1.0f / li0;
            const float inv1 = 1.0f / li1;
            const int rowA = qrow + wq * 16 + g;
            #pragma unroll
            for (int nt = 0; nt < 8; nt++) {
                const int col = nt * 8 + t3 * 2;
                float a0 = (oacc[nt][0] + Oex[(wq*16 + g) * OEXW + col])     * inv0;
                float a1 = (oacc[nt][1] + Oex[(wq*16 + g) * OEXW + col + 1]) * inv0;
                float a2 = (oacc[nt][2] + Oex[(wq*16 + g + 8) * OEXW + col])     * inv1;
                float a3 = (oacc[nt][3] + Oex[(wq*16 + g + 8) * OEXW + col + 1]) * inv1;
                *(float2*)&o[(size_t)rowA * HS + col]       = make_float2(a0, a1);
                *(float2*)&o[(size_t)(rowA + 8) * HS + col] = make_float2(a2, a3);
            }
        }
    }
}

// ===========================================================================
extern "C" void kernel_launch(void* const* d_in, const int* in_sizes, int n_in,
                              void* d_out, int out_size)
{
    const float* x  = (const float*)d_in[0];
    const float* Wq = (const float*)d_in[1];
    const float* Wk = (const float*)d_in[2];
    const float* Wv = (const float*)d_in[3];
    float* out = (float*)d_out;
    (void)in_sizes; (void)n_in; (void)out_size;

    wprep<<<192, 256>>>(Wq, Wk, Wv);

    cudaFuncSetAttribute(qkv_mma, cudaFuncAttributeMaxDynamicSharedMemorySize,
                         QKV_SMEM);
    qkv_mma<<<128, 256, QKV_SMEM>>>(x, Wq, Wk, Wv);

    cudaFuncSetAttribute(attn2, cudaFuncAttributeMaxDynamicSharedMemorySize,
                         AT_SMEM);
    attn2<<<dim3(32, NB), 256, AT_SMEM>>>(out);
}